// round 15
// baseline (speedup 1.0000x reference)
#include <cuda_runtime.h>
#include <cuda_fp16.h>
#include <cstdint>

#define B_ 4
#define N_ 4096
#define F_ 64
#define BM 128
#define BK 32
#define KSPLIT 2
#define NKT_H (N_ / BK / KSPLIT)       // 64 k-tiles per CTA
#define STAGES 3

// stage layout: A fp32 (3 chains x 128 rows x 160B padded) + T fp16 (3 x 64 x 64B)
#define A_ROW_B 160
#define A_CH_B (BM * A_ROW_B)          // 20480
#define A_BYTES (3 * A_CH_B)           // 61440
#define T_CH_B (F_ * 64)               // 4096
#define T_OFF A_BYTES
#define STAGE_BYTES (A_BYTES + 3 * T_CH_B)   // 73728
#define SMEM_BYTES (STAGES * STAGE_BYTES)    // 221184

// T scratch: g_T[c][b][n][k] = fp16_rne( (X[b] @ w_c)[k][n] )
__device__ __half g_T[3][B_][F_][N_];
// split-K partials (no relu): g_P[z][b][row][col]
__device__ float g_P[KSPLIT][B_][N_][F_];

// ---------------------------------------------------------------------------
__device__ __forceinline__ uint32_t smem_u32(const void* p) {
    uint32_t a;
    asm("{ .reg .u64 t; cvta.to.shared.u64 t, %1; cvt.u32.u64 %0, t; }"
        : "=r"(a) : "l"(p));
    return a;
}
__device__ __forceinline__ void ldsm4(uint32_t* r, uint32_t addr) {
    asm volatile("ldmatrix.sync.aligned.m8n8.x4.shared.b16 {%0,%1,%2,%3}, [%4];"
                 : "=r"(r[0]), "=r"(r[1]), "=r"(r[2]), "=r"(r[3]) : "r"(addr));
}
__device__ __forceinline__ uint32_t lds_cvt(uint32_t addr) {
    float x, y;
    asm volatile("ld.shared.v2.f32 {%0,%1}, [%2];" : "=f"(x), "=f"(y) : "r"(addr));
    __half2 h = __floats2half2_rn(x, y);
    return *(uint32_t*)&h;
}
__device__ __forceinline__ void mma16816(float* d, const uint32_t* a,
                                         uint32_t b0, uint32_t b1) {
    asm volatile("mma.sync.aligned.m16n8k16.row.col.f32.f16.f16.f32 "
                 "{%0,%1,%2,%3}, {%4,%5,%6,%7}, {%8,%9}, {%0,%1,%2,%3};"
                 : "+f"(d[0]), "+f"(d[1]), "+f"(d[2]), "+f"(d[3])
                 : "r"(a[0]), "r"(a[1]), "r"(a[2]), "r"(a[3]), "r"(b0), "r"(b1));
}
__device__ __forceinline__ uint32_t packh2(float x, float y) {
    __half2 h = __floats2half2_rn(x, y);
    return *(uint32_t*)&h;
}

// ---------------------------------------------------------------------------
// Kernel 1: g_T[c][b][g][m] = fp16( sum_f X[b][m][f] * w_c[f][g] )
// ---------------------------------------------------------------------------
__global__ void __launch_bounds__(256)
compute_T_kernel(const float* __restrict__ X,
                 const float* __restrict__ w0,
                 const float* __restrict__ w1,
                 const float* __restrict__ w2) {
    const int c = blockIdx.z;
    const int b = blockIdx.y;
    const int m0 = blockIdx.x * 64;
    const float* w = (c == 0) ? w0 : (c == 1) ? w1 : w2;

    __shared__ float sX[64 * 68];
    __shared__ float sW[64 * 68];

    const int tid = threadIdx.x;
    {
        const int q = tid & 15;
        const int r = tid >> 4;
        #pragma unroll
        for (int j = 0; j < 4; j++) {
            const int row = r + 16 * j;
            *(float4*)(sX + row * 68 + q * 4) =
                *(const float4*)(X + ((size_t)b * N_ + m0 + row) * F_ + q * 4);
            *(float4*)(sW + row * 68 + q * 4) =
                *(const float4*)(w + (size_t)row * F_ + q * 4);
        }
    }
    __syncthreads();

    const int row = tid & 63;            // distinct per lane -> 1 wavefront
    const int g0  = (tid >> 6) * 16;     // uniform per warp -> broadcast

    float acc[16];
    #pragma unroll
    for (int i = 0; i < 16; i++) acc[i] = 0.f;

    #pragma unroll 8
    for (int f = 0; f < 64; f++) {
        const float x = sX[row * 68 + f];
        #pragma unroll
        for (int j = 0; j < 4; j++) {
            float4 wv = *(const float4*)(sW + f * 68 + g0 + j * 4);
            acc[j * 4 + 0] += x * wv.x;
            acc[j * 4 + 1] += x * wv.y;
            acc[j * 4 + 2] += x * wv.z;
            acc[j * 4 + 3] += x * wv.w;
        }
    }
    __syncthreads();

    #pragma unroll
    for (int j = 0; j < 4; j++)
        *(float4*)(sX + row * 68 + g0 + j * 4) =
            make_float4(acc[j*4+0], acc[j*4+1], acc[j*4+2], acc[j*4+3]);
    __syncthreads();

    const int g  = tid >> 2;
    const int ms = (tid & 3) * 16;
    uint32_t h[8];
    #pragma unroll
    for (int i = 0; i < 8; i++)
        h[i] = packh2(sX[(ms + 2*i) * 68 + g], sX[(ms + 2*i + 1) * 68 + g]);
    __half* out = &g_T[c][b][g][m0 + ms];
    ((uint4*)out)[0] = make_uint4(h[0], h[1], h[2], h[3]);
    ((uint4*)out)[1] = make_uint4(h[4], h[5], h[6], h[7]);
}

// ---------------------------------------------------------------------------
// Kernel 2: split-K partial P[z][b] = A_chains[k-half z] @ T[k-half z]
// grid (32, 4, 2) = 256 CTAs -> fills all 148 SMs with work-stealing.
// Engine identical to R14: 3-stage cp.async ring, refill-at-top, 8 warps.
// ---------------------------------------------------------------------------
__global__ void __launch_bounds__(256, 1)
gnn_main_kernel(const float* __restrict__ A0,
                const float* __restrict__ A1,
                const float* __restrict__ A2) {
    extern __shared__ char smem[];
    const uint32_t sb = smem_u32(smem);
    const int tid = threadIdx.x;
    const int b = blockIdx.y;
    const int zz = blockIdx.z;               // k-half
    const int rowBase = blockIdx.x * BM;
    const int kBase = zz * (N_ / KSPLIT);    // element offset in k

    const float* Ap[3];
    Ap[0] = A0 + (size_t)b * N_ * N_ + kBase;
    Ap[1] = A1 + (size_t)b * N_ * N_ + kBase;
    Ap[2] = A2 + (size_t)b * N_ * N_ + kBase;

    // A cp.async map: 12 x 16B per thread (384 rows x 8 chunks)
    const float* aSrc[12];
    uint32_t aDst[12];
    #pragma unroll
    for (int j = 0; j < 12; j++) {
        const int id  = tid + 256 * j;          // 0..3071
        const int row = id >> 3;                // 0..383 (chain*128 + r)
        const int ch  = id & 7;
        const int c   = row >> 7;
        const int r   = row & 127;
        aSrc[j] = Ap[c] + (size_t)(rowBase + r) * N_ + ch * 4;
        aDst[j] = (uint32_t)(row * A_ROW_B + ch * 16);
    }
    // T cp.async map: 3 x 16B per thread
    const __half* tSrc[3];
    uint32_t tDst[3];
    #pragma unroll
    for (int j = 0; j < 3; j++) {
        const int id = tid + 256 * j;
        const int c  = id >> 8;
        const int n  = (id >> 2) & 63;
        const int ch = id & 3;
        tSrc[j] = &g_T[c][b][n][0] + kBase + ch * 8;
        tDst[j] = (uint32_t)(T_OFF + c * T_CH_B + n * 64
                             + 16 * (ch ^ ((n >> 1) & 3)));
    }

    #define CP_STAGE(kt, slot) do {                                            \
        const uint32_t _so = sb + (uint32_t)(slot) * STAGE_BYTES;              \
        const int _k0 = (kt) * BK;                                             \
        _Pragma("unroll")                                                      \
        for (int j = 0; j < 12; j++)                                           \
            asm volatile("cp.async.cg.shared.global [%0], [%1], 16;"           \
                         :: "r"(_so + aDst[j]), "l"(aSrc[j] + _k0) : "memory");\
        _Pragma("unroll")                                                      \
        for (int j = 0; j < 3; j++)                                            \
            asm volatile("cp.async.cg.shared.global [%0], [%1], 16;"           \
                         :: "r"(_so + tDst[j]), "l"(tSrc[j] + _k0) : "memory");\
        asm volatile("cp.async.commit_group;" ::: "memory");                   \
    } while (0)

    // fragment geometry: 8 warps, warp tile 16(M) x 64(N)
    const int lane = tid & 31;
    const int warp = tid >> 5;
    const int mrow = lane >> 2;
    const int kp   = lane & 3;
    const int row16 = lane & 15;
    const int cbit  = lane >> 4;
    const uint32_t swz = (uint32_t)((row16 >> 1) & 3);
    const uint32_t aFragOff = (uint32_t)((warp * 16 + mrow) * A_ROW_B + kp * 8);
    const uint32_t bRowOff  = (uint32_t)(T_OFF + row16 * 64);

    float acc[8][4];
    #pragma unroll
    for (int nt = 0; nt < 8; nt++)
        #pragma unroll
        for (int i = 0; i < 4; i++) acc[nt][i] = 0.f;

    // prologue: stages 0,1 in flight
    CP_STAGE(0, 0);
    CP_STAGE(1, 1);

    for (int s = 0; s < NKT_H; s++) {
        const int slot = s % 3;
        asm volatile("cp.async.wait_group 1;" ::: "memory");
        __syncthreads();

        // refill slot (s+2)%3 first (read at iter s-1; all warps past barrier)
        if (s + 2 < NKT_H) {
            CP_STAGE(s + 2, (s + 2) % 3);
        } else {
            asm volatile("cp.async.commit_group;" ::: "memory");
        }

        const uint32_t stBase = sb + (uint32_t)slot * STAGE_BYTES;
        #pragma unroll
        for (int c = 0; c < 3; c++) {
            const uint32_t aCh = stBase + c * A_CH_B + aFragOff;
            const uint32_t bCh = stBase + c * T_CH_B + bRowOff;
            #pragma unroll
            for (int ks = 0; ks < 2; ks++) {
                uint32_t a[4];
                const uint32_t ak = aCh + ks * 64;
                a[0] = lds_cvt(ak);
                a[1] = lds_cvt(ak + 8 * A_ROW_B);
                a[2] = lds_cvt(ak + 32);
                a[3] = lds_cvt(ak + 8 * A_ROW_B + 32);
                const uint32_t kch = 16u * ((uint32_t)((ks << 1) | cbit) ^ swz);
                #pragma unroll
                for (int nt = 0; nt < 4; nt++) {
                    uint32_t bb[4];
                    ldsm4(bb, bCh + nt * 1024 + kch);
                    mma16816(acc[2*nt],     a, bb[0], bb[2]);
                    mma16816(acc[2*nt + 1], a, bb[1], bb[3]);
                }
            }
        }
    }

    // epilogue: store partial (no relu)
    float* P = &g_P[zz][b][0][0];
    #pragma unroll
    for (int nt = 0; nt < 8; nt++) {
        const int r0  = rowBase + warp * 16 + (lane >> 2);
        const int col = nt * 8 + (lane & 3) * 2;
        *(float2*)(P + (size_t)r0 * F_ + col) =
            make_float2(acc[nt][0], acc[nt][1]);
        *(float2*)(P + (size_t)(r0 + 8) * F_ + col) =
            make_float2(acc[nt][2], acc[nt][3]);
    }
}

// ---------------------------------------------------------------------------
// Kernel 3: Y = relu(P0 + P1)
// ---------------------------------------------------------------------------
__global__ void __launch_bounds__(256)
reduce_kernel(float* __restrict__ Y) {
    const int i = blockIdx.x * 256 + threadIdx.x;    // float4 index
    const float4* P0 = (const float4*)&g_P[0][0][0][0];
    const float4* P1 = (const float4*)&g_P[1][0][0][0];
    float4 a = P0[i];
    float4 b = P1[i];
    float4 o;
    o.x = fmaxf(a.x + b.x, 0.f);
    o.y = fmaxf(a.y + b.y, 0.f);
    o.z = fmaxf(a.z + b.z, 0.f);
    o.w = fmaxf(a.w + b.w, 0.f);
    ((float4*)Y)[i] = o;
}

// ---------------------------------------------------------------------------
extern "C" void kernel_launch(void* const* d_in, const int* in_sizes, int n_in,
                              void* d_out, int out_size) {
    (void)in_sizes; (void)n_in; (void)out_size;
    const float* X  = (const float*)d_in[0];
    const float* A0 = (const float*)d_in[1];
    const float* A1 = (const float*)d_in[2];
    const float* A2 = (const float*)d_in[3];
    const float* w0 = (const float*)d_in[4];
    const float* w1 = (const float*)d_in[5];
    const float* w2 = (const float*)d_in[6];
    float* Y = (float*)d_out;

    dim3 g1(N_ / 64, B_, 3);
    compute_T_kernel<<<g1, 256>>>(X, w0, w1, w2);

    cudaFuncSetAttribute(gnn_main_kernel,
                         cudaFuncAttributeMaxDynamicSharedMemorySize, SMEM_BYTES);
    dim3 g2(N_ / BM, B_, KSPLIT);
    gnn_main_kernel<<<g2, 256, SMEM_BYTES>>>(A0, A1, A2);

    const int nvec4 = B_ * N_ * F_ / 4;              // 262144
    reduce_kernel<<<nvec4 / 256, 256>>>(Y);
}

// round 16
// speedup vs baseline: 1.0961x; 1.0961x over previous
#include <cuda_runtime.h>
#include <cuda.h>
#include <cuda_fp16.h>
#include <cstdint>

#define B_ 4
#define N_ 4096
#define F_ 64
#define BM 128
#define BK 32
#define NKT (N_ / BK)                  // 128
#define STAGES 3

// stage layout (TMA-filled): A fp32 SW128 (3 x 128 rows x 128B) + T fp16 SW64 (3 x 64 x 64B)
#define A_CH_B (BM * 128)              // 16384
#define A_BYTES (3 * A_CH_B)           // 49152
#define T_CH_B (F_ * 64)               // 4096
#define T_OFF A_BYTES
#define STAGE_BYTES (A_BYTES + 3 * T_CH_B)   // 61440 (1024-multiple)
#define SMEM_REQ (1024 + STAGES * STAGE_BYTES)  // 185344

// T scratch: g_T[c][b][n][k] = fp16_rne( (X[b] @ w_c)[k][n] )
__device__ __half g_T[3][B_][F_][N_];

// ---------------------------------------------------------------------------
__device__ __forceinline__ uint32_t smem_u32(const void* p) {
    uint32_t a;
    asm("{ .reg .u64 t; cvta.to.shared.u64 t, %1; cvt.u32.u64 %0, t; }"
        : "=r"(a) : "l"(p));
    return a;
}
__device__ __forceinline__ void ldsm4(uint32_t* r, uint32_t addr) {
    asm volatile("ldmatrix.sync.aligned.m8n8.x4.shared.b16 {%0,%1,%2,%3}, [%4];"
                 : "=r"(r[0]), "=r"(r[1]), "=r"(r[2]), "=r"(r[3]) : "r"(addr));
}
__device__ __forceinline__ uint32_t lds_cvt(uint32_t addr) {
    float x, y;
    asm volatile("ld.shared.v2.f32 {%0,%1}, [%2];" : "=f"(x), "=f"(y) : "r"(addr));
    __half2 h = __floats2half2_rn(x, y);
    return *(uint32_t*)&h;
}
__device__ __forceinline__ void mma16816(float* d, const uint32_t* a,
                                         uint32_t b0, uint32_t b1) {
    asm volatile("mma.sync.aligned.m16n8k16.row.col.f32.f16.f16.f32 "
                 "{%0,%1,%2,%3}, {%4,%5,%6,%7}, {%8,%9}, {%0,%1,%2,%3};"
                 : "+f"(d[0]), "+f"(d[1]), "+f"(d[2]), "+f"(d[3])
                 : "r"(a[0]), "r"(a[1]), "r"(a[2]), "r"(a[3]), "r"(b0), "r"(b1));
}
__device__ __forceinline__ uint32_t packh2(float x, float y) {
    __half2 h = __floats2half2_rn(x, y);
    return *(uint32_t*)&h;
}
__device__ __forceinline__ void mbar_init(uint32_t a, uint32_t cnt) {
    asm volatile("mbarrier.init.shared.b64 [%0], %1;" :: "r"(a), "r"(cnt) : "memory");
}
__device__ __forceinline__ void mbar_expect_tx(uint32_t a, uint32_t bytes) {
    asm volatile("mbarrier.arrive.expect_tx.shared.b64 _, [%0], %1;"
                 :: "r"(a), "r"(bytes) : "memory");
}
__device__ __forceinline__ void mbar_wait(uint32_t a, uint32_t par) {
    asm volatile(
        "{\n\t.reg .pred P;\n\t"
        "WL_%=:\n\t"
        "mbarrier.try_wait.parity.acquire.cta.shared::cta.b64 P, [%0], %1, 0x989680;\n\t"
        "@P bra.uni WD_%=;\n\t"
        "bra.uni WL_%=;\n\t"
        "WD_%=:\n\t}"
        :: "r"(a), "r"(par) : "memory");
}
__device__ __forceinline__ void tma3d(uint32_t dst, const CUtensorMap* m,
                                      int x, int y, int z, uint32_t mb) {
    asm volatile(
        "cp.async.bulk.tensor.3d.shared::cta.global.tile.mbarrier::complete_tx::bytes "
        "[%0], [%1, {%2, %3, %4}], [%5];"
        :: "r"(dst), "l"(m), "r"(x), "r"(y), "r"(z), "r"(mb) : "memory");
}

// ---------------------------------------------------------------------------
// Kernel 1: g_T[c][b][g][m] = fp16( sum_f X[b][m][f] * w_c[f][g] )
// ---------------------------------------------------------------------------
__global__ void __launch_bounds__(256)
compute_T_kernel(const float* __restrict__ X,
                 const float* __restrict__ w0,
                 const float* __restrict__ w1,
                 const float* __restrict__ w2) {
    const int c = blockIdx.z;
    const int b = blockIdx.y;
    const int m0 = blockIdx.x * 64;
    const float* w = (c == 0) ? w0 : (c == 1) ? w1 : w2;

    __shared__ float sX[64 * 68];
    __shared__ float sW[64 * 68];

    const int tid = threadIdx.x;
    {
        const int q = tid & 15;
        const int r = tid >> 4;
        #pragma unroll
        for (int j = 0; j < 4; j++) {
            const int row = r + 16 * j;
            *(float4*)(sX + row * 68 + q * 4) =
                *(const float4*)(X + ((size_t)b * N_ + m0 + row) * F_ + q * 4);
            *(float4*)(sW + row * 68 + q * 4) =
                *(const float4*)(w + (size_t)row * F_ + q * 4);
        }
    }
    __syncthreads();

    const int row = tid & 63;
    const int g0  = (tid >> 6) * 16;

    float acc[16];
    #pragma unroll
    for (int i = 0; i < 16; i++) acc[i] = 0.f;

    #pragma unroll 8
    for (int f = 0; f < 64; f++) {
        const float x = sX[row * 68 + f];
        #pragma unroll
        for (int j = 0; j < 4; j++) {
            float4 wv = *(const float4*)(sW + f * 68 + g0 + j * 4);
            acc[j * 4 + 0] += x * wv.x;
            acc[j * 4 + 1] += x * wv.y;
            acc[j * 4 + 2] += x * wv.z;
            acc[j * 4 + 3] += x * wv.w;
        }
    }
    __syncthreads();

    #pragma unroll
    for (int j = 0; j < 4; j++)
        *(float4*)(sX + row * 68 + g0 + j * 4) =
            make_float4(acc[j*4+0], acc[j*4+1], acc[j*4+2], acc[j*4+3]);
    __syncthreads();

    const int g  = tid >> 2;
    const int ms = (tid & 3) * 16;
    uint32_t h[8];
    #pragma unroll
    for (int i = 0; i < 8; i++)
        h[i] = packh2(sX[(ms + 2*i) * 68 + g], sX[(ms + 2*i + 1) * 68 + g]);
    __half* out = &g_T[c][b][g][m0 + ms];
    ((uint4*)out)[0] = make_uint4(h[0], h[1], h[2], h[3]);
    ((uint4*)out)[1] = make_uint4(h[4], h[5], h[6], h[7]);
}

// ---------------------------------------------------------------------------
// Kernel 2: Y[b] = relu(A0@T0 + A1@T1 + A2@T2)   [R14 engine, TMA fills]
// grid (32, 4), block 256 (8 warps, warp tile 16x64).
// Fills: thread 0 issues 6 TMA loads/stage into a 3-slot ring; mbarrier
// (expect_tx) tracks completion. Refill slot (s+2)%3 at top after the block
// barrier (last read at iter s-1 -> race-free). Warps: fragments + mma only.
// ---------------------------------------------------------------------------
__global__ void __launch_bounds__(256, 1)
gnn_main_kernel(const __grid_constant__ CUtensorMap dA0,
                const __grid_constant__ CUtensorMap dA1,
                const __grid_constant__ CUtensorMap dA2,
                const __grid_constant__ CUtensorMap dT,
                float* __restrict__ Y) {
    extern __shared__ char smem_raw[];
    const uint32_t sb0 = smem_u32(smem_raw);
    const uint32_t sb  = (sb0 + 1023u) & ~1023u;   // 1024-align for TMA swizzle
    const uint32_t MBAR = sb0;                      // 3 mbarriers in the slack
    const int tid = threadIdx.x;
    const int b = blockIdx.y;
    const int rowBase = blockIdx.x * BM;

    if (tid == 0) {
        #pragma unroll
        for (int i = 0; i < STAGES; i++) mbar_init(MBAR + 8 * i, 1);
    }
    __syncthreads();

    const CUtensorMap* pA[3] = {&dA0, &dA1, &dA2};

    #define TMA_STAGE(kt, slot) do {                                           \
        const uint32_t _mb = MBAR + 8 * (slot);                                \
        const uint32_t _so = sb + (uint32_t)(slot) * STAGE_BYTES;              \
        const int _k0 = (kt) * BK;                                             \
        mbar_expect_tx(_mb, (uint32_t)STAGE_BYTES);                            \
        _Pragma("unroll")                                                      \
        for (int c = 0; c < 3; c++)                                            \
            tma3d(_so + c * A_CH_B, pA[c], _k0, rowBase, b, _mb);              \
        _Pragma("unroll")                                                      \
        for (int c = 0; c < 3; c++)                                            \
            tma3d(_so + T_OFF + c * T_CH_B, &dT, _k0, 0, c * 4 + b, _mb);      \
    } while (0)

    // fragment geometry: 8 warps, warp tile 16(M) x 64(N)
    const int lane = tid & 31;
    const int warp = tid >> 5;
    const int mrow = lane >> 2;        // 0..7
    const int kp   = lane & 3;
    const int row16 = lane & 15;
    const int cbit  = lane >> 4;
    const uint32_t swz = (uint32_t)((row16 >> 1) & 3);          // T (SW64)
    const uint32_t aRowOff = (uint32_t)((warp * 16 + mrow) * 128);
    const uint32_t bRowOff = (uint32_t)(T_OFF + row16 * 64);
    const uint32_t kpb = (uint32_t)((kp & 1) * 8);
    const uint32_t mxor = (uint32_t)mrow;                        // A SW128 xor

    float acc[8][4];
    #pragma unroll
    for (int nt = 0; nt < 8; nt++)
        #pragma unroll
        for (int i = 0; i < 4; i++) acc[nt][i] = 0.f;

    // prologue: stages 0,1 in flight
    if (tid == 0) {
        TMA_STAGE(0, 0);
        TMA_STAGE(1, 1);
    }

    for (int s = 0; s < NKT; s++) {
        const int slot = s % 3;
        __syncthreads();              // all reads of iter s-1 complete

        // refill slot (s+2)%3 = (s-1)%3 — safe after the barrier above
        if (tid == 0 && s + 2 < NKT) {
            const int ns = (s + 2) % 3;
            TMA_STAGE(s + 2, ns);
        }

        // wait for stage s fill (parity flips each time a slot is reused)
        mbar_wait(MBAR + 8 * slot, (uint32_t)((s / 3) & 1));

        const uint32_t stBase = sb + (uint32_t)slot * STAGE_BYTES;
        #pragma unroll
        for (int c = 0; c < 3; c++) {
            const uint32_t aCh = stBase + c * A_CH_B + aRowOff;
            const uint32_t bCh = stBase + c * T_CH_B + bRowOff;
            #pragma unroll
            for (int ks = 0; ks < 2; ks++) {
                // A fragment m16k16 from SW128 rows: chunk c0 = ks*4 + kp/2
                const uint32_t c0 = (uint32_t)(ks * 4 + (kp >> 1));
                const uint32_t o0 = 16u * (c0 ^ mxor) + kpb;
                const uint32_t o2 = 16u * ((c0 + 2) ^ mxor) + kpb;
                uint32_t a[4];
                a[0] = lds_cvt(aCh + o0);
                a[1] = lds_cvt(aCh + 1024 + o0);     // +8 rows
                a[2] = lds_cvt(aCh + o2);
                a[3] = lds_cvt(aCh + 1024 + o2);
                const uint32_t kch = 16u * ((uint32_t)((ks << 1) | cbit) ^ swz);
                #pragma unroll
                for (int nt = 0; nt < 4; nt++) {
                    uint32_t bb[4];
                    ldsm4(bb, bCh + nt * 1024 + kch);
                    mma16816(acc[2*nt],     a, bb[0], bb[2]);
                    mma16816(acc[2*nt + 1], a, bb[1], bb[3]);
                }
            }
        }
    }

    // epilogue: relu + store
    #pragma unroll
    for (int nt = 0; nt < 8; nt++) {
        const int r0  = rowBase + warp * 16 + (lane >> 2);
        const int col = nt * 8 + (lane & 3) * 2;
        float2 v0 = make_float2(fmaxf(acc[nt][0], 0.f), fmaxf(acc[nt][1], 0.f));
        float2 v1 = make_float2(fmaxf(acc[nt][2], 0.f), fmaxf(acc[nt][3], 0.f));
        *(float2*)(Y + ((size_t)b * N_ + r0) * F_ + col)     = v0;
        *(float2*)(Y + ((size_t)b * N_ + r0 + 8) * F_ + col) = v1;
    }
}

// ---------------------------------------------------------------------------
// Host side
// ---------------------------------------------------------------------------
typedef CUresult (*PFN_enc_t)(CUtensorMap*, CUtensorMapDataType, cuuint32_t, void*,
                              const cuuint64_t*, const cuuint64_t*, const cuuint32_t*,
                              const cuuint32_t*, CUtensorMapInterleave, CUtensorMapSwizzle,
                              CUtensorMapL2promotion, CUtensorMapFloatOOBfill);

static PFN_enc_t get_enc() {
    static PFN_enc_t fn = nullptr;
    if (!fn) {
        void* p = nullptr;
        cudaDriverEntryPointQueryResult qr;
        if (cudaGetDriverEntryPointByVersion("cuTensorMapEncodeTiled", &p, 12000,
                                             cudaEnableDefault, &qr) != cudaSuccess || !p) {
            cudaGetDriverEntryPoint("cuTensorMapEncodeTiled", &p, cudaEnableDefault, &qr);
        }
        fn = (PFN_enc_t)p;
    }
    return fn;
}

static void enc3d(CUtensorMap* m, void* ptr, CUtensorMapDataType dt,
                  uint64_t d0, uint64_t d1, uint64_t d2,
                  uint64_t s1, uint64_t s2, uint32_t b0, uint32_t b1,
                  CUtensorMapSwizzle sw) {
    cuuint64_t dims[3] = {d0, d1, d2};
    cuuint64_t str[2]  = {s1, s2};
    cuuint32_t box[3]  = {b0, b1, 1};
    cuuint32_t es[3]   = {1, 1, 1};
    get_enc()(m, dt, 3, ptr, dims, str, box, es,
              CU_TENSOR_MAP_INTERLEAVE_NONE, sw,
              CU_TENSOR_MAP_L2_PROMOTION_L2_128B, CU_TENSOR_MAP_FLOAT_OOB_FILL_NONE);
}

extern "C" void kernel_launch(void* const* d_in, const int* in_sizes, int n_in,
                              void* d_out, int out_size) {
    (void)in_sizes; (void)n_in; (void)out_size;
    const float* X  = (const float*)d_in[0];
    const float* A0 = (const float*)d_in[1];
    const float* A1 = (const float*)d_in[2];
    const float* A2 = (const float*)d_in[3];
    const float* w0 = (const float*)d_in[4];
    const float* w1 = (const float*)d_in[5];
    const float* w2 = (const float*)d_in[6];
    float* Y = (float*)d_out;

    dim3 g1(N_ / 64, B_, 3);
    compute_T_kernel<<<g1, 256>>>(X, w0, w1, w2);

    void* tsym = nullptr;
    cudaGetSymbolAddress(&tsym, g_T);

    // A_c: [k=4096][m=4096][b=4] fp32, box 32x128, SW128 (128B rows)
    CUtensorMap mA0, mA1, mA2, mT;
    enc3d(&mA0, (void*)A0, CU_TENSOR_MAP_DATA_TYPE_FLOAT32,
          N_, N_, B_, (uint64_t)N_ * 4, (uint64_t)N_ * N_ * 4,
          BK, BM, CU_TENSOR_MAP_SWIZZLE_128B);
    enc3d(&mA1, (void*)A1, CU_TENSOR_MAP_DATA_TYPE_FLOAT32,
          N_, N_, B_, (uint64_t)N_ * 4, (uint64_t)N_ * N_ * 4,
          BK, BM, CU_TENSOR_MAP_SWIZZLE_128B);
    enc3d(&mA2, (void*)A2, CU_TENSOR_MAP_DATA_TYPE_FLOAT32,
          N_, N_, B_, (uint64_t)N_ * 4, (uint64_t)N_ * N_ * 4,
          BK, BM, CU_TENSOR_MAP_SWIZZLE_128B);
    // T: [k=4096][n=64][cb=12] fp16, box 32x64, SW64 (64B rows)
    enc3d(&mT, tsym, CU_TENSOR_MAP_DATA_TYPE_UINT16,
          N_, F_, 12, (uint64_t)N_ * 2, (uint64_t)F_ * N_ * 2,
          BK, F_, CU_TENSOR_MAP_SWIZZLE_64B);

    cudaFuncSetAttribute(gnn_main_kernel,
                         cudaFuncAttributeMaxDynamicSharedMemorySize, SMEM_REQ);
    dim3 g2(N_ / BM, B_);
    gnn_main_kernel<<<g2, 256, SMEM_REQ>>>(mA0, mA1, mA2, mT, Y);
}

// round 17
// speedup vs baseline: 1.1810x; 1.0775x over previous
#include <cuda_runtime.h>
#include <cuda.h>
#include <cuda_fp16.h>
#include <cstdint>

#define B_ 4
#define N_ 4096
#define F_ 64
#define BM 64
#define BK 32
#define NKT (N_ / BK)                  // 128
#define STAGES 3

// stage layout (TMA-filled): A fp32 SW128 (3 x 64 rows x 128B) + T fp16 SW64 (3 x 64 x 64B)
#define A_CH_B (BM * 128)              // 8192
#define A_BYTES (3 * A_CH_B)           // 24576
#define T_CH_B (F_ * 64)               // 4096
#define T_OFF A_BYTES
#define STAGE_BYTES (A_BYTES + 3 * T_CH_B)   // 36864 (1024-multiple)
#define SMEM_REQ (1024 + STAGES * STAGE_BYTES)  // 111616 -> 2 CTAs/SM

// T scratch: g_T[c][b][n][k] = fp16_rne( (X[b] @ w_c)[k][n] )
__device__ __half g_T[3][B_][F_][N_];

// ---------------------------------------------------------------------------
__device__ __forceinline__ uint32_t smem_u32(const void* p) {
    uint32_t a;
    asm("{ .reg .u64 t; cvta.to.shared.u64 t, %1; cvt.u32.u64 %0, t; }"
        : "=r"(a) : "l"(p));
    return a;
}
__device__ __forceinline__ void ldsm4(uint32_t* r, uint32_t addr) {
    asm volatile("ldmatrix.sync.aligned.m8n8.x4.shared.b16 {%0,%1,%2,%3}, [%4];"
                 : "=r"(r[0]), "=r"(r[1]), "=r"(r[2]), "=r"(r[3]) : "r"(addr));
}
__device__ __forceinline__ uint32_t lds_cvt(uint32_t addr) {
    float x, y;
    asm volatile("ld.shared.v2.f32 {%0,%1}, [%2];" : "=f"(x), "=f"(y) : "r"(addr));
    __half2 h = __floats2half2_rn(x, y);
    return *(uint32_t*)&h;
}
__device__ __forceinline__ void mma16816(float* d, const uint32_t* a,
                                         uint32_t b0, uint32_t b1) {
    asm volatile("mma.sync.aligned.m16n8k16.row.col.f32.f16.f16.f32 "
                 "{%0,%1,%2,%3}, {%4,%5,%6,%7}, {%8,%9}, {%0,%1,%2,%3};"
                 : "+f"(d[0]), "+f"(d[1]), "+f"(d[2]), "+f"(d[3])
                 : "r"(a[0]), "r"(a[1]), "r"(a[2]), "r"(a[3]), "r"(b0), "r"(b1));
}
__device__ __forceinline__ uint32_t packh2(float x, float y) {
    __half2 h = __floats2half2_rn(x, y);
    return *(uint32_t*)&h;
}
__device__ __forceinline__ void mbar_init(uint32_t a, uint32_t cnt) {
    asm volatile("mbarrier.init.shared.b64 [%0], %1;" :: "r"(a), "r"(cnt) : "memory");
}
__device__ __forceinline__ void mbar_expect_tx(uint32_t a, uint32_t bytes) {
    asm volatile("mbarrier.arrive.expect_tx.shared.b64 _, [%0], %1;"
                 :: "r"(a), "r"(bytes) : "memory");
}
__device__ __forceinline__ void mbar_wait(uint32_t a, uint32_t par) {
    asm volatile(
        "{\n\t.reg .pred P;\n\t"
        "WL_%=:\n\t"
        "mbarrier.try_wait.parity.acquire.cta.shared::cta.b64 P, [%0], %1, 0x989680;\n\t"
        "@P bra.uni WD_%=;\n\t"
        "bra.uni WL_%=;\n\t"
        "WD_%=:\n\t}"
        :: "r"(a), "r"(par) : "memory");
}
__device__ __forceinline__ void tma3d(uint32_t dst, const CUtensorMap* m,
                                      int x, int y, int z, uint32_t mb) {
    asm volatile(
        "cp.async.bulk.tensor.3d.shared::cta.global.tile.mbarrier::complete_tx::bytes "
        "[%0], [%1, {%2, %3, %4}], [%5];"
        :: "r"(dst), "l"(m), "r"(x), "r"(y), "r"(z), "r"(mb) : "memory");
}

// ---------------------------------------------------------------------------
// Kernel 1: g_T[c][b][g][m] = fp16( sum_f X[b][m][f] * w_c[f][g] )
// ---------------------------------------------------------------------------
__global__ void __launch_bounds__(256)
compute_T_kernel(const float* __restrict__ X,
                 const float* __restrict__ w0,
                 const float* __restrict__ w1,
                 const float* __restrict__ w2) {
    const int c = blockIdx.z;
    const int b = blockIdx.y;
    const int m0 = blockIdx.x * 64;
    const float* w = (c == 0) ? w0 : (c == 1) ? w1 : w2;

    __shared__ float sX[64 * 68];
    __shared__ float sW[64 * 68];

    const int tid = threadIdx.x;
    {
        const int q = tid & 15;
        const int r = tid >> 4;
        #pragma unroll
        for (int j = 0; j < 4; j++) {
            const int row = r + 16 * j;
            *(float4*)(sX + row * 68 + q * 4) =
                *(const float4*)(X + ((size_t)b * N_ + m0 + row) * F_ + q * 4);
            *(float4*)(sW + row * 68 + q * 4) =
                *(const float4*)(w + (size_t)row * F_ + q * 4);
        }
    }
    __syncthreads();

    const int row = tid & 63;
    const int g0  = (tid >> 6) * 16;

    float acc[16];
    #pragma unroll
    for (int i = 0; i < 16; i++) acc[i] = 0.f;

    #pragma unroll 8
    for (int f = 0; f < 64; f++) {
        const float x = sX[row * 68 + f];
        #pragma unroll
        for (int j = 0; j < 4; j++) {
            float4 wv = *(const float4*)(sW + f * 68 + g0 + j * 4);
            acc[j * 4 + 0] += x * wv.x;
            acc[j * 4 + 1] += x * wv.y;
            acc[j * 4 + 2] += x * wv.z;
            acc[j * 4 + 3] += x * wv.w;
        }
    }
    __syncthreads();

    #pragma unroll
    for (int j = 0; j < 4; j++)
        *(float4*)(sX + row * 68 + g0 + j * 4) =
            make_float4(acc[j*4+0], acc[j*4+1], acc[j*4+2], acc[j*4+3]);
    __syncthreads();

    const int g  = tid >> 2;
    const int ms = (tid & 3) * 16;
    uint32_t h[8];
    #pragma unroll
    for (int i = 0; i < 8; i++)
        h[i] = packh2(sX[(ms + 2*i) * 68 + g], sX[(ms + 2*i + 1) * 68 + g]);
    __half* out = &g_T[c][b][g][m0 + ms];
    ((uint4*)out)[0] = make_uint4(h[0], h[1], h[2], h[3]);
    ((uint4*)out)[1] = make_uint4(h[4], h[5], h[6], h[7]);
}

// ---------------------------------------------------------------------------
// Kernel 2: Y[b] = relu(A0@T0 + A1@T1 + A2@T2)   [TMA engine, 2 CTAs/SM]
// grid (64, 4) = 256 CTAs, block 128 (4 warps, warp tile 16x64).
// Fills: thread 0 issues 6 TMA loads/stage into a 3-slot ring; mbarrier
// tracks completion. Refill slot (s+2)%3 at top after the block barrier.
// ---------------------------------------------------------------------------
__global__ void __launch_bounds__(128, 2)
gnn_main_kernel(const __grid_constant__ CUtensorMap dA0,
                const __grid_constant__ CUtensorMap dA1,
                const __grid_constant__ CUtensorMap dA2,
                const __grid_constant__ CUtensorMap dT,
                float* __restrict__ Y) {
    extern __shared__ char smem_raw[];
    const uint32_t sb0 = smem_u32(smem_raw);
    const uint32_t sb  = (sb0 + 1023u) & ~1023u;   // 1024-align for TMA swizzle
    const uint32_t MBAR = sb0;                      // 3 mbarriers in the slack
    const int tid = threadIdx.x;
    const int b = blockIdx.y;
    const int rowBase = blockIdx.x * BM;

    if (tid == 0) {
        #pragma unroll
        for (int i = 0; i < STAGES; i++) mbar_init(MBAR + 8 * i, 1);
    }
    __syncthreads();

    const CUtensorMap* pA[3] = {&dA0, &dA1, &dA2};

    #define TMA_STAGE(kt, slot) do {                                           \
        const uint32_t _mb = MBAR + 8 * (slot);                                \
        const uint32_t _so = sb + (uint32_t)(slot) * STAGE_BYTES;              \
        const int _k0 = (kt) * BK;                                             \
        mbar_expect_tx(_mb, (uint32_t)STAGE_BYTES);                            \
        _Pragma("unroll")                                                      \
        for (int c = 0; c < 3; c++)                                            \
            tma3d(_so + c * A_CH_B, pA[c], _k0, rowBase, b, _mb);              \
        _Pragma("unroll")                                                      \
        for (int c = 0; c < 3; c++)                                            \
            tma3d(_so + T_OFF + c * T_CH_B, &dT, _k0, 0, c * 4 + b, _mb);      \
    } while (0)

    // fragment geometry: 4 warps, warp tile 16(M) x 64(N)
    const int lane = tid & 31;
    const int warp = tid >> 5;
    const int mrow = lane >> 2;        // 0..7
    const int kp   = lane & 3;
    const int row16 = lane & 15;
    const int cbit  = lane >> 4;
    const uint32_t swz = (uint32_t)((row16 >> 1) & 3);          // T (SW64)
    const uint32_t aRowOff = (uint32_t)((warp * 16 + mrow) * 128);
    const uint32_t bRowOff = (uint32_t)(T_OFF + row16 * 64);
    const uint32_t kpb = (uint32_t)((kp & 1) * 8);
    const uint32_t mxor = (uint32_t)mrow;                        // A SW128 xor

    float acc[8][4];
    #pragma unroll
    for (int nt = 0; nt < 8; nt++)
        #pragma unroll
        for (int i = 0; i < 4; i++) acc[nt][i] = 0.f;

    // prologue: stages 0,1 in flight
    if (tid == 0) {
        TMA_STAGE(0, 0);
        TMA_STAGE(1, 1);
    }

    for (int s = 0; s < NKT; s++) {
        const int slot = s % 3;
        __syncthreads();              // all reads of iter s-1 complete

        // refill slot (s+2)%3 = (s-1)%3 — safe after the barrier above
        if (tid == 0 && s + 2 < NKT) {
            TMA_STAGE(s + 2, (s + 2) % 3);
        }

        // wait for stage s fill
        mbar_wait(MBAR + 8 * slot, (uint32_t)((s / 3) & 1));

        const uint32_t stBase = sb + (uint32_t)slot * STAGE_BYTES;
        #pragma unroll
        for (int c = 0; c < 3; c++) {
            const uint32_t aCh = stBase + c * A_CH_B + aRowOff;
            const uint32_t bCh = stBase + c * T_CH_B + bRowOff;
            #pragma unroll
            for (int ks = 0; ks < 2; ks++) {
                const uint32_t c0 = (uint32_t)(ks * 4 + (kp >> 1));
                const uint32_t o0 = 16u * (c0 ^ mxor) + kpb;
                const uint32_t o2 = 16u * ((c0 + 2) ^ mxor) + kpb;
                uint32_t a[4];
                a[0] = lds_cvt(aCh + o0);
                a[1] = lds_cvt(aCh + 1024 + o0);     // +8 rows
                a[2] = lds_cvt(aCh + o2);
                a[3] = lds_cvt(aCh + 1024 + o2);
                const uint32_t kch = 16u * ((uint32_t)((ks << 1) | cbit) ^ swz);
                #pragma unroll
                for (int nt = 0; nt < 4; nt++) {
                    uint32_t bb[4];
                    ldsm4(bb, bCh + nt * 1024 + kch);
                    mma16816(acc[2*nt],     a, bb[0], bb[2]);
                    mma16816(acc[2*nt + 1], a, bb[1], bb[3]);
                }
            }
        }
    }

    // epilogue: relu + store
    #pragma unroll
    for (int nt = 0; nt < 8; nt++) {
        const int r0  = rowBase + warp * 16 + (lane >> 2);
        const int col = nt * 8 + (lane & 3) * 2;
        float2 v0 = make_float2(fmaxf(acc[nt][0], 0.f), fmaxf(acc[nt][1], 0.f));
        float2 v1 = make_float2(fmaxf(acc[nt][2], 0.f), fmaxf(acc[nt][3], 0.f));
        *(float2*)(Y + ((size_t)b * N_ + r0) * F_ + col)     = v0;
        *(float2*)(Y + ((size_t)b * N_ + r0 + 8) * F_ + col) = v1;
    }
}

// ---------------------------------------------------------------------------
// Host side
// ---------------------------------------------------------------------------
typedef CUresult (*PFN_enc_t)(CUtensorMap*, CUtensorMapDataType, cuuint32_t, void*,
                              const cuuint64_t*, const cuuint64_t*, const cuuint32_t*,
                              const cuuint32_t*, CUtensorMapInterleave, CUtensorMapSwizzle,
                              CUtensorMapL2promotion, CUtensorMapFloatOOBfill);

static PFN_enc_t get_enc() {
    static PFN_enc_t fn = nullptr;
    if (!fn) {
        void* p = nullptr;
        cudaDriverEntryPointQueryResult qr;
        if (cudaGetDriverEntryPointByVersion("cuTensorMapEncodeTiled", &p, 12000,
                                             cudaEnableDefault, &qr) != cudaSuccess || !p) {
            cudaGetDriverEntryPoint("cuTensorMapEncodeTiled", &p, cudaEnableDefault, &qr);
        }
        fn = (PFN_enc_t)p;
    }
    return fn;
}

static void enc3d(CUtensorMap* m, void* ptr, CUtensorMapDataType dt,
                  uint64_t d0, uint64_t d1, uint64_t d2,
                  uint64_t s1, uint64_t s2, uint32_t b0, uint32_t b1,
                  CUtensorMapSwizzle sw) {
    cuuint64_t dims[3] = {d0, d1, d2};
    cuuint64_t str[2]  = {s1, s2};
    cuuint32_t box[3]  = {b0, b1, 1};
    cuuint32_t es[3]   = {1, 1, 1};
    get_enc()(m, dt, 3, ptr, dims, str, box, es,
              CU_TENSOR_MAP_INTERLEAVE_NONE, sw,
              CU_TENSOR_MAP_L2_PROMOTION_L2_128B, CU_TENSOR_MAP_FLOAT_OOB_FILL_NONE);
}

extern "C" void kernel_launch(void* const* d_in, const int* in_sizes, int n_in,
                              void* d_out, int out_size) {
    (void)in_sizes; (void)n_in; (void)out_size;
    const float* X  = (const float*)d_in[0];
    const float* A0 = (const float*)d_in[1];
    const float* A1 = (const float*)d_in[2];
    const float* A2 = (const float*)d_in[3];
    const float* w0 = (const float*)d_in[4];
    const float* w1 = (const float*)d_in[5];
    const float* w2 = (const float*)d_in[6];
    float* Y = (float*)d_out;

    dim3 g1(N_ / 64, B_, 3);
    compute_T_kernel<<<g1, 256>>>(X, w0, w1, w2);

    void* tsym = nullptr;
    cudaGetSymbolAddress(&tsym, g_T);

    // A_c: [k=4096][m=4096][b=4] fp32, box 32x64, SW128 (128B rows)
    CUtensorMap mA0, mA1, mA2, mT;
    enc3d(&mA0, (void*)A0, CU_TENSOR_MAP_DATA_TYPE_FLOAT32,
          N_, N_, B_, (uint64_t)N_ * 4, (uint64_t)N_ * N_ * 4,
          BK, BM, CU_TENSOR_MAP_SWIZZLE_128B);
    enc3d(&mA1, (void*)A1, CU_TENSOR_MAP_DATA_TYPE_FLOAT32,
          N_, N_, B_, (uint64_t)N_ * 4, (uint64_t)N_ * N_ * 4,
          BK, BM, CU_TENSOR_MAP_SWIZZLE_128B);
    enc3d(&mA2, (void*)A2, CU_TENSOR_MAP_DATA_TYPE_FLOAT32,
          N_, N_, B_, (uint64_t)N_ * 4, (uint64_t)N_ * N_ * 4,
          BK, BM, CU_TENSOR_MAP_SWIZZLE_128B);
    // T: [k=4096][n=64][cb=12] fp16, box 32x64, SW64 (64B rows)
    enc3d(&mT, tsym, CU_TENSOR_MAP_DATA_TYPE_UINT16,
          N_, F_, 12, (uint64_t)N_ * 2, (uint64_t)F_ * N_ * 2,
          BK, F_, CU_TENSOR_MAP_SWIZZLE_64B);

    cudaFuncSetAttribute(gnn_main_kernel,
                         cudaFuncAttributeMaxDynamicSharedMemorySize, SMEM_REQ);
    dim3 g2(N_ / BM, B_);
    gnn_main_kernel<<<g2, 128, SMEM_REQ>>>(mA0, mA1, mA2, mT, Y);
}